// round 10
// baseline (speedup 1.0000x reference)
#include <cuda_runtime.h>

namespace {
constexpr int BATCH = 1024;
constexpr int FEAT  = 1024;   // F (bias row in epilogue; weights have FEAT+1 rows)
constexpr int NCOLS = 256;    // per-op output columns
constexpr int NOUT  = 512;

constexpr int BM = 64;
constexpr int BN = 32;
constexpr int BK = 32;
constexpr int TM = 4;         // rows per thread
constexpr int TN = 2;         // cols per thread
constexpr int NTHR = 256;     // 8 warps/CTA; occ 2 -> 16 warps/SM
constexpr int XSTRIDE = BM + 4;        // 68 floats
constexpr int NSTAGE = FEAT / BK;      // 32
}

// Tropical GEMM:
//   dilated[b,n] = max_f ( x[b,f] + D[f,n] )   (out cols 256..511)
//   eroded [b,n] = min_f ( x[b,f] - E[f,n] )   (out cols 0..255)
// Erosion in negated domain: -eroded = max_f((-x) + e); shared fmaxf(acc, x+w)
// inner loop. Bias row handled by one epilogue fmaxf with W[FEAT, n].
__global__ __launch_bounds__(NTHR, 2)
void tropical_gemm(const float* __restrict__ x,
                   const float* __restrict__ dil,
                   const float* __restrict__ ero,
                   float* __restrict__ out)
{
    __shared__ __align__(16) float xs[2][BK][XSTRIDE];
    __shared__ __align__(16) float ws[2][BK][BN];

    const int tid = threadIdx.x;
    const int ct  = blockIdx.x;              // 0..15 : 0-7 erosion, 8-15 dilation
    const bool is_ero = (ct < 8);
    const float sgn = is_ero ? -1.0f : 1.0f;
    const int n0 = (ct & 7) * BN;
    const float* __restrict__ w = is_ero ? ero : dil;
    const int m0 = blockIdx.y * BM;
    const int ocol0 = (is_ero ? 0 : NCOLS) + n0;

    const int tx = tid & 15;                 // col group: cols tx*2 .. tx*2+1
    const int ty = tid >> 4;                 // row group: rows ty*4 .. ty*4+3

    // x loader: 4 threads per row, each loads 8 consecutive k
    const int lxm = tid & 63;                // row within tile
    const int lxk = (tid >> 6) << 3;         // k offset (0,8,16,24)

    // w loader: one float4 per thread: 32k x 32n
    const int wkk = tid >> 3;                // k row 0..31
    const int wc4 = (tid & 7) * 4;           // col 0..28

    float acc[TM][TN];
#pragma unroll
    for (int i = 0; i < TM; ++i)
#pragma unroll
        for (int j = 0; j < TN; ++j)
            acc[i][j] = -__int_as_float(0x7f800000);   // -inf

    float4 xr0, xr1;
    float4 wr;
    const float* xrow = x + (m0 + lxm) * FEAT + lxk;

    // ---- prefetch + store stage 0 ----
    xr0 = *(const float4*)(xrow + 0);
    xr1 = *(const float4*)(xrow + 4);
    wr  = *(const float4*)(w + wkk * NCOLS + n0 + wc4);
    {
        const float xv0[4] = {xr0.x, xr0.y, xr0.z, xr0.w};
        const float xv1[4] = {xr1.x, xr1.y, xr1.z, xr1.w};
#pragma unroll
        for (int i = 0; i < 4; ++i) xs[0][lxk + i][lxm]     = sgn * xv0[i];
#pragma unroll
        for (int i = 0; i < 4; ++i) xs[0][lxk + 4 + i][lxm] = sgn * xv1[i];
        *(float4*)&ws[0][wkk][wc4] = wr;
    }
    __syncthreads();

    for (int s = 0; s < NSTAGE; ++s) {
        const int cur = s & 1;
        if (s + 1 < NSTAGE) {
            const int k0 = (s + 1) * BK;
            xr0 = *(const float4*)(xrow + k0);
            xr1 = *(const float4*)(xrow + k0 + 4);
            wr  = *(const float4*)(w + (k0 + wkk) * NCOLS + n0 + wc4);
        }
#pragma unroll 8
        for (int k = 0; k < BK; ++k) {
            const float4 xv = *(const float4*)&xs[cur][k][ty * 4];
            const float2 wv = *(const float2*)&ws[cur][k][tx * 2];
            const float xa[4] = {xv.x, xv.y, xv.z, xv.w};
            const float wa[2] = {wv.x, wv.y};
#pragma unroll
            for (int i = 0; i < TM; ++i)
#pragma unroll
                for (int j = 0; j < TN; ++j)
                    acc[i][j] = fmaxf(acc[i][j], xa[i] + wa[j]);
        }
        if (s + 1 < NSTAGE) {
            const int nxt = cur ^ 1;
            const float xv0[4] = {xr0.x, xr0.y, xr0.z, xr0.w};
            const float xv1[4] = {xr1.x, xr1.y, xr1.z, xr1.w};
#pragma unroll
            for (int i = 0; i < 4; ++i) xs[nxt][lxk + i][lxm]     = sgn * xv0[i];
#pragma unroll
            for (int i = 0; i < 4; ++i) xs[nxt][lxk + 4 + i][lxm] = sgn * xv1[i];
            *(float4*)&ws[nxt][wkk][wc4] = wr;
            __syncthreads();
        }
    }

    // ---- bias feature: k = FEAT, x contribution is 0 in both domains ----
    {
        const float2 wb = *(const float2*)(w + FEAT * NCOLS + n0 + tx * 2);
        const float wba[2] = {wb.x, wb.y};
#pragma unroll
        for (int i = 0; i < TM; ++i)
#pragma unroll
            for (int j = 0; j < TN; ++j)
                acc[i][j] = fmaxf(acc[i][j], wba[j]);
    }

    // ---- store (negate back for erosion) ----
#pragma unroll
    for (int i = 0; i < TM; ++i) {
        const int row = m0 + ty * 4 + i;
        float2 o;
        o.x = sgn * acc[i][0];
        o.y = sgn * acc[i][1];
        *(float2*)(out + row * NOUT + ocol0 + tx * 2) = o;
    }
}

extern "C" void kernel_launch(void* const* d_in, const int* in_sizes, int n_in,
                              void* d_out, int out_size) {
    const float* x   = (const float*)d_in[0];
    const float* dil = (const float*)d_in[1];
    const float* ero = (const float*)d_in[2];
    float* out = (float*)d_out;
    (void)in_sizes; (void)n_in; (void)out_size;

    dim3 grid(16, BATCH / BM);  // 16 col tiles (8 ero + 8 dil) x 16 row tiles = 256 CTAs
    tropical_gemm<<<grid, NTHR>>>(x, dil, ero, out);
}

// round 13
// speedup vs baseline: 1.1292x; 1.1292x over previous
#include <cuda_runtime.h>

namespace {
constexpr int BATCH = 1024;
constexpr int FEAT  = 1024;   // F; weights have FEAT+1 rows (bias row = FEAT)
constexpr int NCOLS = 256;    // per-op output columns
constexpr int NOUT  = 512;

constexpr int BM = 32;
constexpr int BN = 64;
constexpr int BK = 32;
constexpr int TM = 4;
constexpr int TN = 4;
constexpr int NTHR = 128;
constexpr int XSTRIDE = BM + 4;        // 36 floats
constexpr int KSPLIT = 2;
constexpr int KHALF  = FEAT / KSPLIT;  // 512
constexpr int NSTAGE = KHALF / BK;     // 16
}

// 4MB scratch for split-K partials (negated-domain maxes; combine applies sign).
__device__ float g_partial[KSPLIT][BATCH * NOUT];

// Tropical GEMM, split-K partial:
//   split s covers features [s*KHALF, (s+1)*KHALF) plus the bias row (idempotent
//   under max, so including it in both splits is harmless and keeps code uniform).
// Erosion in negated domain: -eroded = max_f((-x) + e); both halves share the
// fmaxf(acc, x + w) inner loop. Partials stored WITHOUT the final sign flip.
__global__ __launch_bounds__(NTHR, 4)
void tropical_gemm_partial(const float* __restrict__ x,
                           const float* __restrict__ dil,
                           const float* __restrict__ ero)
{
    __shared__ __align__(16) float xs[2][BK][XSTRIDE];
    __shared__ __align__(16) float ws[2][BK][BN];

    const int tid = threadIdx.x;
    const int ct  = blockIdx.x;              // 0..7 : 0-3 erosion tiles, 4-7 dilation
    const bool is_ero = (ct < 4);
    const float sgn = is_ero ? -1.0f : 1.0f;
    const int n0 = (ct & 3) * BN;
    const float* __restrict__ w = is_ero ? ero : dil;
    const int m0 = blockIdx.y * BM;
    const int split = blockIdx.z;            // 0 or 1
    const int kbase = split * KHALF;
    const int ocol0 = (is_ero ? 0 : NCOLS) + n0;
    float* __restrict__ part = g_partial[split];

    const int tx = tid & 15;                 // output col group (tx*4)
    const int ty = tid >> 4;                 // output row group (ty*4)

    // x loader: each thread loads 8 consecutive k of one row (transposed store)
    const int lxm = tid & 31;
    const int lxk = (tid >> 5) << 3;

    float acc[TM][TN];
#pragma unroll
    for (int i = 0; i < TM; ++i)
#pragma unroll
        for (int j = 0; j < TN; ++j)
            acc[i][j] = -__int_as_float(0x7f800000);   // -inf

    float4 xr0, xr1;
    float4 wr[4];
    const float* xrow = x + (m0 + lxm) * FEAT + kbase + lxk;
    const float* wbase = w + (size_t)kbase * NCOLS;

    // ---- prefetch + store stage 0 ----
    xr0 = *(const float4*)(xrow + 0);
    xr1 = *(const float4*)(xrow + 4);
#pragma unroll
    for (int j = 0; j < 4; ++j) {
        const int fid = tid + NTHR * j;
        const int kk = fid >> 4, c4 = fid & 15;
        wr[j] = *(const float4*)(wbase + kk * NCOLS + n0 + c4 * 4);
    }
    {
        const float xv0[4] = {xr0.x, xr0.y, xr0.z, xr0.w};
        const float xv1[4] = {xr1.x, xr1.y, xr1.z, xr1.w};
#pragma unroll
        for (int i = 0; i < 4; ++i) xs[0][lxk + i][lxm]     = sgn * xv0[i];
#pragma unroll
        for (int i = 0; i < 4; ++i) xs[0][lxk + 4 + i][lxm] = sgn * xv1[i];
#pragma unroll
        for (int j = 0; j < 4; ++j) {
            const int fid = tid + NTHR * j;
            const int kk = fid >> 4, c4 = fid & 15;
            *(float4*)&ws[0][kk][c4 * 4] = wr[j];
        }
    }
    __syncthreads();

    for (int s = 0; s < NSTAGE; ++s) {
        const int cur = s & 1;
        if (s + 1 < NSTAGE) {
            const int k0 = (s + 1) * BK;
            xr0 = *(const float4*)(xrow + k0);
            xr1 = *(const float4*)(xrow + k0 + 4);
#pragma unroll
            for (int j = 0; j < 4; ++j) {
                const int fid = tid + NTHR * j;
                const int kk = fid >> 4, c4 = fid & 15;
                wr[j] = *(const float4*)(wbase + (k0 + kk) * NCOLS + n0 + c4 * 4);
            }
        }
#pragma unroll 8
        for (int k = 0; k < BK; ++k) {
            const float4 xv = *(const float4*)&xs[cur][k][ty * 4];
            const float4 wv = *(const float4*)&ws[cur][k][tx * 4];
            const float xa[4] = {xv.x, xv.y, xv.z, xv.w};
            const float wa[4] = {wv.x, wv.y, wv.z, wv.w};
#pragma unroll
            for (int i = 0; i < TM; ++i)
#pragma unroll
                for (int j = 0; j < TN; ++j)
                    acc[i][j] = fmaxf(acc[i][j], xa[i] + wa[j]);
        }
        if (s + 1 < NSTAGE) {
            const int nxt = cur ^ 1;
            const float xv0[4] = {xr0.x, xr0.y, xr0.z, xr0.w};
            const float xv1[4] = {xr1.x, xr1.y, xr1.z, xr1.w};
#pragma unroll
            for (int i = 0; i < 4; ++i) xs[nxt][lxk + i][lxm]     = sgn * xv0[i];
#pragma unroll
            for (int i = 0; i < 4; ++i) xs[nxt][lxk + 4 + i][lxm] = sgn * xv1[i];
#pragma unroll
            for (int j = 0; j < 4; ++j) {
                const int fid = tid + NTHR * j;
                const int kk = fid >> 4, c4 = fid & 15;
                *(float4*)&ws[nxt][kk][c4 * 4] = wr[j];
            }
            __syncthreads();
        }
    }

    // ---- bias row (k = FEAT): x contribution is 0 in both domains; idempotent ----
    {
        const float4 wb = *(const float4*)(w + (size_t)FEAT * NCOLS + n0 + tx * 4);
        const float wba[4] = {wb.x, wb.y, wb.z, wb.w};
#pragma unroll
        for (int i = 0; i < TM; ++i)
#pragma unroll
            for (int j = 0; j < TN; ++j)
                acc[i][j] = fmaxf(acc[i][j], wba[j]);
    }

    // ---- store partial (still negated domain for erosion) ----
#pragma unroll
    for (int i = 0; i < TM; ++i) {
        const int row = m0 + ty * 4 + i;
        float4 o;
        o.x = acc[i][0];
        o.y = acc[i][1];
        o.z = acc[i][2];
        o.w = acc[i][3];
        *(float4*)(part + row * NOUT + ocol0 + tx * 4) = o;
    }
}

// out = sgn(col) * max(p0, p1);  sgn = -1 for erosion cols [0,256), +1 for dilation.
__global__ __launch_bounds__(256)
void combine_partials(float* __restrict__ out)
{
    const int i = blockIdx.x * 256 + threadIdx.x;       // float4 index
    const int c = (i * 4) & (NOUT - 1);                 // column of first lane
    const float sgn = (c < NCOLS) ? -1.0f : 1.0f;
    const float4 a = ((const float4*)g_partial[0])[i];
    const float4 b = ((const float4*)g_partial[1])[i];
    float4 o;
    o.x = sgn * fmaxf(a.x, b.x);
    o.y = sgn * fmaxf(a.y, b.y);
    o.z = sgn * fmaxf(a.z, b.z);
    o.w = sgn * fmaxf(a.w, b.w);
    ((float4*)out)[i] = o;
}

extern "C" void kernel_launch(void* const* d_in, const int* in_sizes, int n_in,
                              void* d_out, int out_size) {
    const float* x   = (const float*)d_in[0];
    const float* dil = (const float*)d_in[1];
    const float* ero = (const float*)d_in[2];
    float* out = (float*)d_out;
    (void)in_sizes; (void)n_in; (void)out_size;

    dim3 grid(8, BATCH / BM, KSPLIT);   // 8 col tiles x 32 row tiles x 2 k-splits = 512 CTAs
    tropical_gemm_partial<<<grid, NTHR>>>(x, dil, ero);

    const int n4 = BATCH * NOUT / 4;    // 131072 float4s
    combine_partials<<<n4 / 256, 256>>>(out);
}

// round 17
// speedup vs baseline: 1.1410x; 1.0105x over previous
#include <cuda_runtime.h>

namespace {
constexpr int BATCH = 1024;
constexpr int FEAT  = 1024;   // F; weights have FEAT+1 rows (bias row = FEAT)
constexpr int NCOLS = 256;    // per-op output columns
constexpr int NOUT  = 512;

constexpr int BM = 32;
constexpr int BN = 64;
constexpr int BK = 32;
constexpr int TM = 4;
constexpr int TN = 4;
constexpr int NTHR = 128;
constexpr int XSTRIDE = BM + 4;        // 36 floats
constexpr int KSPLIT = 2;
constexpr int KHALF  = FEAT / KSPLIT;  // 512
constexpr int NSTAGE = KHALF / BK;     // 16
}

// 4MB scratch for split-K partials (negated-domain maxes; combine applies sign).
__device__ float g_partial[KSPLIT][BATCH * NOUT];

// acc = max(acc, a + b), with the add forced into FFMA-imm form:
// fma.rn.f32 d, a, 1.0, b  ==  a + b exactly (RN, multiplier 1.0).
// FFMA src1-imm runs at rt_SMSP=1 on the fma pipe (vs FADD rt=2), halving
// fma-pipe occupancy so the alu pipe (FMNMX) becomes the sole long pole.
__device__ __forceinline__ float addmax(float acc, float a, float b) {
    float s;
    asm("fma.rn.f32 %0, %1, 0f3F800000, %2;" : "=f"(s) : "f"(a), "f"(b));
    return fmaxf(acc, s);
}

// Tropical GEMM, split-K partial (split s covers [s*KHALF,(s+1)*KHALF) + bias
// row, idempotent under max). Erosion in negated domain; partials stored
// without the final sign flip.
__global__ __launch_bounds__(NTHR, 4)
void tropical_gemm_partial(const float* __restrict__ x,
                           const float* __restrict__ dil,
                           const float* __restrict__ ero)
{
    __shared__ __align__(16) float xs[2][BK][XSTRIDE];
    __shared__ __align__(16) float ws[2][BK][BN];

    const int tid = threadIdx.x;
    const int ct  = blockIdx.x;              // 0..7 : 0-3 erosion tiles, 4-7 dilation
    const bool is_ero = (ct < 4);
    const float sgn = is_ero ? -1.0f : 1.0f;
    const int n0 = (ct & 3) * BN;
    const float* __restrict__ w = is_ero ? ero : dil;
    const int m0 = blockIdx.y * BM;
    const int split = blockIdx.z;            // 0 or 1
    const int kbase = split * KHALF;
    const int ocol0 = (is_ero ? 0 : NCOLS) + n0;
    float* __restrict__ part = g_partial[split];

    const int tx = tid & 15;                 // output col group (tx*4)
    const int ty = tid >> 4;                 // output row group (ty*4)

    // x loader: each thread loads 8 consecutive k of one row (transposed store)
    const int lxm = tid & 31;
    const int lxk = (tid >> 5) << 3;

    float acc[TM][TN];
#pragma unroll
    for (int i = 0; i < TM; ++i)
#pragma unroll
        for (int j = 0; j < TN; ++j)
            acc[i][j] = -__int_as_float(0x7f800000);   // -inf

    float4 xr0, xr1;
    float4 wr[4];
    const float* xrow = x + (m0 + lxm) * FEAT + kbase + lxk;
    const float* wbase = w + (size_t)kbase * NCOLS;

    // ---- prefetch + store stage 0 ----
    xr0 = *(const float4*)(xrow + 0);
    xr1 = *(const float4*)(xrow + 4);
#pragma unroll
    for (int j = 0; j < 4; ++j) {
        const int fid = tid + NTHR * j;
        const int kk = fid >> 4, c4 = fid & 15;
        wr[j] = *(const float4*)(wbase + kk * NCOLS + n0 + c4 * 4);
    }
    {
        const float xv0[4] = {xr0.x, xr0.y, xr0.z, xr0.w};
        const float xv1[4] = {xr1.x, xr1.y, xr1.z, xr1.w};
#pragma unroll
        for (int i = 0; i < 4; ++i) xs[0][lxk + i][lxm]     = sgn * xv0[i];
#pragma unroll
        for (int i = 0; i < 4; ++i) xs[0][lxk + 4 + i][lxm] = sgn * xv1[i];
#pragma unroll
        for (int j = 0; j < 4; ++j) {
            const int fid = tid + NTHR * j;
            const int kk = fid >> 4, c4 = fid & 15;
            *(float4*)&ws[0][kk][c4 * 4] = wr[j];
        }
    }
    __syncthreads();

    for (int s = 0; s < NSTAGE; ++s) {
        const int cur = s & 1;
        if (s + 1 < NSTAGE) {
            const int k0 = (s + 1) * BK;
            xr0 = *(const float4*)(xrow + k0);
            xr1 = *(const float4*)(xrow + k0 + 4);
#pragma unroll
            for (int j = 0; j < 4; ++j) {
                const int fid = tid + NTHR * j;
                const int kk = fid >> 4, c4 = fid & 15;
                wr[j] = *(const float4*)(wbase + (k0 + kk) * NCOLS + n0 + c4 * 4);
            }
        }
#pragma unroll 8
        for (int k = 0; k < BK; ++k) {
            const float4 xv = *(const float4*)&xs[cur][k][ty * 4];
            const float4 wv = *(const float4*)&ws[cur][k][tx * 4];
            const float xa[4] = {xv.x, xv.y, xv.z, xv.w};
            const float wa[4] = {wv.x, wv.y, wv.z, wv.w};
#pragma unroll
            for (int i = 0; i < TM; ++i)
#pragma unroll
                for (int j = 0; j < TN; ++j)
                    acc[i][j] = addmax(acc[i][j], xa[i], wa[j]);
        }
        if (s + 1 < NSTAGE) {
            const int nxt = cur ^ 1;
            const float xv0[4] = {xr0.x, xr0.y, xr0.z, xr0.w};
            const float xv1[4] = {xr1.x, xr1.y, xr1.z, xr1.w};
#pragma unroll
            for (int i = 0; i < 4; ++i) xs[nxt][lxk + i][lxm]     = sgn * xv0[i];
#pragma unroll
            for (int i = 0; i < 4; ++i) xs[nxt][lxk + 4 + i][lxm] = sgn * xv1[i];
#pragma unroll
            for (int j = 0; j < 4; ++j) {
                const int fid = tid + NTHR * j;
                const int kk = fid >> 4, c4 = fid & 15;
                *(float4*)&ws[nxt][kk][c4 * 4] = wr[j];
            }
            __syncthreads();
        }
    }

    // ---- bias row (k = FEAT): x contribution is 0 in both domains; idempotent ----
    {
        const float4 wb = *(const float4*)(w + (size_t)FEAT * NCOLS + n0 + tx * 4);
        const float wba[4] = {wb.x, wb.y, wb.z, wb.w};
#pragma unroll
        for (int i = 0; i < TM; ++i)
#pragma unroll
            for (int j = 0; j < TN; ++j)
                acc[i][j] = fmaxf(acc[i][j], wba[j]);
    }

    // ---- store partial (still negated domain for erosion) ----
#pragma unroll
    for (int i = 0; i < TM; ++i) {
        const int row = m0 + ty * 4 + i;
        float4 o;
        o.x = acc[i][0];
        o.y = acc[i][1];
        o.z = acc[i][2];
        o.w = acc[i][3];
        *(float4*)(part + row * NOUT + ocol0 + tx * 4) = o;
    }
}

// out = sgn(col) * max(p0, p1);  sgn = -1 for erosion cols [0,256), +1 for dilation.
__global__ __launch_bounds__(256)
void combine_partials(float* __restrict__ out)
{
    const int i = blockIdx.x * 256 + threadIdx.x;       // float4 index
    const int c = (i * 4) & (NOUT - 1);                 // column of first lane
    const float sgn = (c < NCOLS) ? -1.0f : 1.0f;
    const float4 a = ((const float4*)g_partial[0])[i];
    const float4 b = ((const float4*)g_partial[1])[i];
    float4 o;
    o.x = sgn * fmaxf(a.x, b.x);
    o.y = sgn * fmaxf(a.y, b.y);
    o.z = sgn * fmaxf(a.z, b.z);
    o.w = sgn * fmaxf(a.w, b.w);
    ((float4*)out)[i] = o;
}

extern "C" void kernel_launch(void* const* d_in, const int* in_sizes, int n_in,
                              void* d_out, int out_size) {
    const float* x   = (const float*)d_in[0];
    const float* dil = (const float*)d_in[1];
    const float* ero = (const float*)d_in[2];
    float* out = (float*)d_out;
    (void)in_sizes; (void)n_in; (void)out_size;

    dim3 grid(8, BATCH / BM, KSPLIT);   // 8 col tiles x 32 row tiles x 2 k-splits = 512 CTAs
    tropical_gemm_partial<<<grid, NTHR>>>(x, dil, ero);

    const int n4 = BATCH * NOUT / 4;    // 131072 float4s
    combine_partials<<<n4 / 256, 256>>>(out);
}